// round 2
// baseline (speedup 1.0000x reference)
#include <cuda_runtime.h>
#include <math.h>

#define BSZ 2
#define SEQ 2048
#define DIM 512
#define NH 8
#define DK 64

// Scratch (device globals: allocation-free per harness rules)
__device__ float g_Q[BSZ*SEQ*DIM];
__device__ float g_K[BSZ*SEQ*DIM];
__device__ float g_V[BSZ*SEQ*DIM];
__device__ float g_H[BSZ*SEQ*DIM];
__device__ int   g_lens[4];   // [rowlen_b0, rowlen_b1, collen_b0, collen_b1]

// ---------------------------------------------------------------------------
// Pad-mask length reduction: lengths are the ROW SUMS of the masks.
// grid = 4 blocks (which = 0: row b0, 1: row b1, 2: col b0, 3: col b1)
// ---------------------------------------------------------------------------
__global__ void lens_kernel(const int* __restrict__ rowm, const int* __restrict__ colm){
    int which = blockIdx.x;
    const int* p = ((which < 2) ? rowm : colm) + (which & 1) * SEQ;
    __shared__ int red[256];
    int t = threadIdx.x;
    int s = 0;
    for (int i = t; i < SEQ; i += 256) s += p[i];
    red[t] = s; __syncthreads();
    for (int off = 128; off > 0; off >>= 1){
        if (t < off) red[t] += red[t + off];
        __syncthreads();
    }
    if (t == 0) g_lens[which] = red[0];
}

// ---------------------------------------------------------------------------
// Out[m,n] = sum_k X[m,k] * W[n,k] + bias[n]   (torch Linear: x @ W.T + b)
// BM=BN=64, BK=16, 256 threads, 4x4 register tile per thread.
// Both X and W are K-contiguous; both are transposed on smem store.
// ---------------------------------------------------------------------------
__global__ __launch_bounds__(256)
void gemm64(const float* __restrict__ X, const float* __restrict__ W,
            const float* __restrict__ bias, float* __restrict__ Out){
    __shared__ float As[16][68];
    __shared__ float Bs[16][68];
    int bm = blockIdx.y * 64, bn = blockIdx.x * 64;
    int tid = threadIdx.x;
    int tx = tid & 15, ty = tid >> 4;
    int lr = tid >> 2, lc = (tid & 3) << 2;
    float acc[4][4] = {};
    for (int k0 = 0; k0 < DIM; k0 += 16){
        float4 av = *(const float4*)(X + (size_t)(bm + lr) * DIM + k0 + lc);
        float4 bv = *(const float4*)(W + (size_t)(bn + lr) * DIM + k0 + lc);
        As[lc + 0][lr] = av.x; As[lc + 1][lr] = av.y;
        As[lc + 2][lr] = av.z; As[lc + 3][lr] = av.w;
        Bs[lc + 0][lr] = bv.x; Bs[lc + 1][lr] = bv.y;
        Bs[lc + 2][lr] = bv.z; Bs[lc + 3][lr] = bv.w;
        __syncthreads();
#pragma unroll
        for (int k = 0; k < 16; k++){
            float a[4], b[4];
#pragma unroll
            for (int i = 0; i < 4; i++) a[i] = As[k][ty * 4 + i];
#pragma unroll
            for (int j = 0; j < 4; j++) b[j] = Bs[k][tx * 4 + j];
#pragma unroll
            for (int i = 0; i < 4; i++)
#pragma unroll
                for (int j = 0; j < 4; j++)
                    acc[i][j] = fmaf(a[i], b[j], acc[i][j]);
        }
        __syncthreads();
    }
#pragma unroll
    for (int i = 0; i < 4; i++){
#pragma unroll
        for (int j = 0; j < 4; j++){
            Out[(size_t)(bm + ty * 4 + i) * DIM + bn + tx * 4 + j] =
                acc[i][j] + bias[bn + tx * 4 + j];
        }
    }
}

// ---------------------------------------------------------------------------
// Flash-attention block: grid (S/64, H, B), 256 threads.
// BQ = BKt = 64, DK = 64. Online softmax; O in registers (4x4 per thread).
// Masking: valid = (q < row_len) && (k < col_len) && (k <= q); invalid rows
// (l == 0) output exactly 0 (matches reference nan_to_num).
// ---------------------------------------------------------------------------
__global__ __launch_bounds__(256)
void attn_kernel(const float* __restrict__ Q, const float* __restrict__ K,
                 const float* __restrict__ V, float* __restrict__ H){
    extern __shared__ float sm[];
    float* Qs   = sm;               // [64][68] row-major (q, d)
    float* Kt   = sm + 64 * 68;     // [64][68] d-major   (d, k)
    float* Vs   = sm + 2 * 64 * 68; // [64][68] row-major (k, d)
    float* Ss   = sm + 3 * 64 * 68; // [64][68] scores/probs (q, k)
    float* mrow = sm + 4 * 64 * 68; // [64]
    float* lrow = mrow + 64;        // [64]
    float* frow = lrow + 64;        // [64]

    int b = blockIdx.z, h = blockIdx.y, q0 = blockIdx.x * 64;
    int tid = threadIdx.x;
    int tx = tid & 15, ty = tid >> 4;
    int row_len = g_lens[b], col_len = g_lens[2 + b];

    const float* Qb = Q + ((size_t)b * SEQ + q0) * DIM + h * DK;
#pragma unroll
    for (int p = 0; p < 4; p++){
        int r = (tid >> 4) + p * 16;
        int c = (tid & 15) << 2;
        *(float4*)(Qs + r * 68 + c) = *(const float4*)(Qb + (size_t)r * DIM + c);
    }
    if (tid < 64){ mrow[tid] = -INFINITY; lrow[tid] = 0.f; }
    float o[4][4] = {};
    int kend = min(col_len, q0 + 64);
    __syncthreads();

    for (int kt = 0; kt < kend; kt += 64){
        const float* Kb = K + ((size_t)b * SEQ + kt) * DIM + h * DK;
        const float* Vb = V + ((size_t)b * SEQ + kt) * DIM + h * DK;
#pragma unroll
        for (int p = 0; p < 4; p++){
            int r = (tid >> 4) + p * 16;
            int c = (tid & 15) << 2;
            float4 kv = *(const float4*)(Kb + (size_t)r * DIM + c);
            Kt[(c + 0) * 68 + r] = kv.x; Kt[(c + 1) * 68 + r] = kv.y;
            Kt[(c + 2) * 68 + r] = kv.z; Kt[(c + 3) * 68 + r] = kv.w;
            *(float4*)(Vs + r * 68 + c) = *(const float4*)(Vb + (size_t)r * DIM + c);
        }
        __syncthreads();

        // S = Q @ K^T
        float s[4][4] = {};
#pragma unroll
        for (int d = 0; d < 64; d++){
            float a[4], bb[4];
#pragma unroll
            for (int i = 0; i < 4; i++) a[i] = Qs[(ty * 4 + i) * 68 + d];
#pragma unroll
            for (int j = 0; j < 4; j++) bb[j] = Kt[d * 68 + tx * 4 + j];
#pragma unroll
            for (int i = 0; i < 4; i++)
#pragma unroll
                for (int j = 0; j < 4; j++)
                    s[i][j] = fmaf(a[i], bb[j], s[i][j]);
        }
        // scale + mask, stage to shared
#pragma unroll
        for (int i = 0; i < 4; i++){
            int qg = q0 + ty * 4 + i;
#pragma unroll
            for (int j = 0; j < 4; j++){
                int kg = kt + tx * 4 + j;
                bool valid = (qg < row_len) && (kg < col_len) && (kg <= qg);
                Ss[(ty * 4 + i) * 68 + tx * 4 + j] =
                    valid ? s[i][j] * 0.125f : -INFINITY;
            }
        }
        __syncthreads();

        // online softmax: warp w owns rows [w*8, w*8+8)
        int warp = tid >> 5, lane = tid & 31;
        for (int r8 = 0; r8 < 8; r8++){
            int r = warp * 8 + r8;
            float v0 = Ss[r * 68 + lane], v1 = Ss[r * 68 + lane + 32];
            float mt = fmaxf(v0, v1);
#pragma unroll
            for (int off = 16; off > 0; off >>= 1)
                mt = fmaxf(mt, __shfl_xor_sync(0xffffffffu, mt, off));
            float mo = mrow[r];
            float mn = fmaxf(mo, mt);
            float p0, p1, fac;
            if (mn == -INFINITY){ p0 = 0.f; p1 = 0.f; fac = 1.f; }
            else {
                fac = (mo == -INFINITY) ? 0.f : __expf(mo - mn);
                p0  = (v0 == -INFINITY) ? 0.f : __expf(v0 - mn);
                p1  = (v1 == -INFINITY) ? 0.f : __expf(v1 - mn);
            }
            float sum = p0 + p1;
#pragma unroll
            for (int off = 16; off > 0; off >>= 1)
                sum += __shfl_xor_sync(0xffffffffu, sum, off);
            Ss[r * 68 + lane] = p0; Ss[r * 68 + lane + 32] = p1;
            if (lane == 0){ mrow[r] = mn; frow[r] = fac; lrow[r] = lrow[r] * fac + sum; }
        }
        __syncthreads();

        // rescale O, then O += P @ V
        float f[4];
#pragma unroll
        for (int i = 0; i < 4; i++) f[i] = frow[ty * 4 + i];
#pragma unroll
        for (int i = 0; i < 4; i++)
#pragma unroll
            for (int j = 0; j < 4; j++) o[i][j] *= f[i];
#pragma unroll
        for (int k = 0; k < 64; k++){
            float a[4], bb[4];
#pragma unroll
            for (int i = 0; i < 4; i++) a[i] = Ss[(ty * 4 + i) * 68 + k];
#pragma unroll
            for (int j = 0; j < 4; j++) bb[j] = Vs[k * 68 + tx * 4 + j];
#pragma unroll
            for (int i = 0; i < 4; i++)
#pragma unroll
                for (int j = 0; j < 4; j++)
                    o[i][j] = fmaf(a[i], bb[j], o[i][j]);
        }
        __syncthreads();
    }

    // epilogue: O / l  (l == 0 -> 0, matching nan_to_num)
    float* Hb = H + ((size_t)b * SEQ + q0) * DIM + h * DK;
#pragma unroll
    for (int i = 0; i < 4; i++){
        float l = lrow[ty * 4 + i];
        float linv = (l > 0.f) ? 1.f / l : 0.f;
#pragma unroll
        for (int j = 0; j < 4; j++)
            Hb[(size_t)(ty * 4 + i) * DIM + tx * 4 + j] = o[i][j] * linv;
    }
}

// ---------------------------------------------------------------------------
extern "C" void kernel_launch(void* const* d_in, const int* in_sizes, int n_in,
                              void* d_out, int out_size){
    (void)in_sizes; (void)n_in; (void)out_size;
    const float* in_Q = (const float*)d_in[0];
    const float* in_K = (const float*)d_in[1];
    const float* in_V = (const float*)d_in[2];
    const int*   rowm = (const int*)  d_in[3];
    const int*   colm = (const int*)  d_in[4];
    const float* W_Q  = (const float*)d_in[5];
    const float* b_Q  = (const float*)d_in[6];
    const float* W_K  = (const float*)d_in[7];
    const float* b_K  = (const float*)d_in[8];
    const float* W_V  = (const float*)d_in[9];
    const float* b_V  = (const float*)d_in[10];
    const float* W_O  = (const float*)d_in[11];
    const float* b_O  = (const float*)d_in[12];
    float* out = (float*)d_out;

    float *gQ, *gK, *gV, *gH;
    cudaGetSymbolAddress((void**)&gQ, g_Q);
    cudaGetSymbolAddress((void**)&gK, g_K);
    cudaGetSymbolAddress((void**)&gV, g_V);
    cudaGetSymbolAddress((void**)&gH, g_H);

    lens_kernel<<<4, 256>>>(rowm, colm);

    dim3 gg(DIM / 64, (BSZ * SEQ) / 64);
    gemm64<<<gg, 256>>>(in_Q, W_Q, b_Q, gQ);
    gemm64<<<gg, 256>>>(in_K, W_K, b_K, gK);
    gemm64<<<gg, 256>>>(in_V, W_V, b_V, gV);

    size_t smem = (size_t)(4 * 64 * 68 + 192) * sizeof(float);
    cudaFuncSetAttribute(attn_kernel, cudaFuncAttributeMaxDynamicSharedMemorySize,
                         (int)smem);
    attn_kernel<<<dim3(SEQ / 64, NH, BSZ), 256, smem>>>(gQ, gK, gV, gH);

    gemm64<<<gg, 256>>>(gH, W_O, b_O, out);
}

// round 5
// speedup vs baseline: 1.4390x; 1.4390x over previous
#include <cuda_runtime.h>
#include <cuda_bf16.h>
#include <stdint.h>
#include <math.h>

#define BSZ 2
#define SEQ 2048
#define DIM 512
#define NH 8
#define DK 64
#define MROWS (BSZ*SEQ)   // 4096

// ------------------------- scratch (device globals) -------------------------
__device__ float g_Q[MROWS*DIM];
__device__ float g_K[MROWS*DIM];
__device__ float g_V[MROWS*DIM];
__device__ float g_H[MROWS*DIM];
__device__ int   g_lens[4];

// ------------------------- helpers -------------------------
__device__ __forceinline__ uint32_t smem_u32(const void* p){
    uint32_t a;
    asm("{ .reg .u64 t; cvta.to.shared.u64 t, %1; cvt.u32.u64 %0, t; }" : "=r"(a) : "l"(p));
    return a;
}
__device__ __forceinline__ void ldsm4(uint32_t* r, uint32_t addr){
    asm volatile("ldmatrix.sync.aligned.m8n8.x4.shared.b16 {%0,%1,%2,%3}, [%4];"
                 : "=r"(r[0]), "=r"(r[1]), "=r"(r[2]), "=r"(r[3]) : "r"(addr));
}
__device__ __forceinline__ void mma16816(float* d, const uint32_t* a, uint32_t b0, uint32_t b1){
    asm volatile(
        "mma.sync.aligned.m16n8k16.row.col.f32.bf16.bf16.f32 "
        "{%0,%1,%2,%3}, {%4,%5,%6,%7}, {%8,%9}, {%0,%1,%2,%3};"
        : "+f"(d[0]), "+f"(d[1]), "+f"(d[2]), "+f"(d[3])
        : "r"(a[0]), "r"(a[1]), "r"(a[2]), "r"(a[3]), "r"(b0), "r"(b1));
}
__device__ __forceinline__ uint32_t pack_bf16(__nv_bfloat16 lo, __nv_bfloat16 hi){
    __nv_bfloat162 p(lo, hi);
    return *reinterpret_cast<uint32_t*>(&p);
}

// ---------------------------------------------------------------------------
// lens: pad-mask row sums
// ---------------------------------------------------------------------------
__global__ void lens_kernel(const int* __restrict__ rowm, const int* __restrict__ colm){
    int which = blockIdx.x;
    const int* p = ((which < 2) ? rowm : colm) + (which & 1) * SEQ;
    __shared__ int red[256];
    int t = threadIdx.x;
    int s = 0;
    for (int i = t; i < SEQ; i += 256) s += p[i];
    red[t] = s; __syncthreads();
    for (int off = 128; off > 0; off >>= 1){
        if (t < off) red[t] += red[t + off];
        __syncthreads();
    }
    if (t == 0) g_lens[which] = red[0];
}

// ---------------------------------------------------------------------------
// HMMA GEMM: Out[4096,512] = X @ W^T + b  via mma.sync bf16 hi/lo split.
// Grid (DIM/64, MROWS/128), 256 threads (8 warps, 4(m) x 2(n), 32x32 each).
// Per K-chunk of 64: fp32 tiles converted in-kernel to bf16 hi/lo smem
// (stride 72 elems = 144B, ldmatrix conflict-free), 3 mma products, fp32 acc.
// ---------------------------------------------------------------------------
#define SA_STRIDE 72            // bf16 elems per smem row
#define SA_BYTES  (128*144)     // Ahi/Alo tile bytes (18432)
#define SB_BYTES  (64*144)      // Bhi/Blo tile bytes (9216)
#define OFF_AHI 0
#define OFF_ALO (SA_BYTES)
#define OFF_BHI (2*SA_BYTES)
#define OFF_BLO (2*SA_BYTES + SB_BYTES)
#define GEMM_SMEM (2*SA_BYTES + 2*SB_BYTES)   // 55296

__global__ __launch_bounds__(256)
void gemm_mma(const float* __restrict__ X, const float* __restrict__ W,
              const float* __restrict__ bias, float* __restrict__ Out){
    extern __shared__ char smem[];
    uint32_t sb = smem_u32(smem);
    int tid = threadIdx.x, wid = tid >> 5, lane = tid & 31;
    int bn = blockIdx.x * 64, bm = blockIdx.y * 128;
    int wm = (wid & 3) * 32;     // warp m offset within CTA tile
    int wn = (wid >> 2) * 32;    // warp n offset

    float acc[2][4][4] = {};

    for (int c = 0; c < 8; c++){
        int k0 = c * 64;
        // ---- fill A (128x64) hi/lo ----
#pragma unroll
        for (int p = 0; p < 8; p++){
            int idx = p * 256 + tid;
            int row = idx >> 4;
            int kq  = (idx & 15) << 2;
            float4 v = *(const float4*)(X + (size_t)(bm + row) * DIM + k0 + kq);
            __nv_bfloat16 h0 = __float2bfloat16_rn(v.x);
            __nv_bfloat16 h1 = __float2bfloat16_rn(v.y);
            __nv_bfloat16 h2 = __float2bfloat16_rn(v.z);
            __nv_bfloat16 h3 = __float2bfloat16_rn(v.w);
            uint32_t hi01 = pack_bf16(h0, h1), hi23 = pack_bf16(h2, h3);
            uint32_t lo01 = pack_bf16(__float2bfloat16_rn(v.x - __bfloat162float(h0)),
                                      __float2bfloat16_rn(v.y - __bfloat162float(h1)));
            uint32_t lo23 = pack_bf16(__float2bfloat16_rn(v.z - __bfloat162float(h2)),
                                      __float2bfloat16_rn(v.w - __bfloat162float(h3)));
            uint32_t off = (uint32_t)(row * 144 + kq * 2);
            asm volatile("st.shared.v2.b32 [%0], {%1,%2};"
                         :: "r"(sb + OFF_AHI + off), "r"(hi01), "r"(hi23) : "memory");
            asm volatile("st.shared.v2.b32 [%0], {%1,%2};"
                         :: "r"(sb + OFF_ALO + off), "r"(lo01), "r"(lo23) : "memory");
        }
        // ---- fill B (64x64) hi/lo ----
#pragma unroll
        for (int p = 0; p < 4; p++){
            int idx = p * 256 + tid;
            int row = idx >> 4;
            int kq  = (idx & 15) << 2;
            float4 v = *(const float4*)(W + (size_t)(bn + row) * DIM + k0 + kq);
            __nv_bfloat16 h0 = __float2bfloat16_rn(v.x);
            __nv_bfloat16 h1 = __float2bfloat16_rn(v.y);
            __nv_bfloat16 h2 = __float2bfloat16_rn(v.z);
            __nv_bfloat16 h3 = __float2bfloat16_rn(v.w);
            uint32_t hi01 = pack_bf16(h0, h1), hi23 = pack_bf16(h2, h3);
            uint32_t lo01 = pack_bf16(__float2bfloat16_rn(v.x - __bfloat162float(h0)),
                                      __float2bfloat16_rn(v.y - __bfloat162float(h1)));
            uint32_t lo23 = pack_bf16(__float2bfloat16_rn(v.z - __bfloat162float(h2)),
                                      __float2bfloat16_rn(v.w - __bfloat162float(h3)));
            uint32_t off = (uint32_t)(row * 144 + kq * 2);
            asm volatile("st.shared.v2.b32 [%0], {%1,%2};"
                         :: "r"(sb + OFF_BHI + off), "r"(hi01), "r"(hi23) : "memory");
            asm volatile("st.shared.v2.b32 [%0], {%1,%2};"
                         :: "r"(sb + OFF_BLO + off), "r"(lo01), "r"(lo23) : "memory");
        }
        __syncthreads();

        // ---- mma over 4 k16 steps ----
#pragma unroll
        for (int ks = 0; ks < 4; ks++){
            int kk = ks * 16;
            uint32_t lrow = (uint32_t)(lane & 15), lhalf = (uint32_t)(lane >> 4);
            uint32_t ah[2][4], al[2][4];
#pragma unroll
            for (int mi = 0; mi < 2; mi++){
                uint32_t off = (uint32_t)(((wm + mi * 16 + lrow) * SA_STRIDE + kk) * 2 + lhalf * 16);
                ldsm4(ah[mi], sb + OFF_AHI + off);
                ldsm4(al[mi], sb + OFF_ALO + off);
            }
            uint32_t bh[2][4], bl[2][4];
#pragma unroll
            for (int nj = 0; nj < 2; nj++){
                uint32_t off = (uint32_t)(((wn + nj * 16 + lrow) * SA_STRIDE + kk) * 2 + lhalf * 16);
                ldsm4(bh[nj], sb + OFF_BHI + off);
                ldsm4(bl[nj], sb + OFF_BLO + off);
            }
#pragma unroll
            for (int mi = 0; mi < 2; mi++){
#pragma unroll
                for (int j = 0; j < 4; j++){
                    // x4 ldsm matrix order: m0=rows0-7/k0-7, m1=rows8-15/k0-7,
                    // m2=rows0-7/k8-15, m3=rows8-15/k8-15 -> n8 tile j:
                    uint32_t b0h = bh[j >> 1][j & 1], b1h = bh[j >> 1][(j & 1) + 2];
                    uint32_t b0l = bl[j >> 1][j & 1], b1l = bl[j >> 1][(j & 1) + 2];
                    mma16816(acc[mi][j], ah[mi], b0h, b1h);
                    mma16816(acc[mi][j], al[mi], b0h, b1h);
                    mma16816(acc[mi][j], ah[mi], b0l, b1l);
                }
            }
        }
        __syncthreads();
    }

    // ---- epilogue: d-frag scatter + bias ----
    int r0 = lane >> 2, c0 = (lane & 3) * 2;
#pragma unroll
    for (int mi = 0; mi < 2; mi++){
#pragma unroll
        for (int j = 0; j < 4; j++){
            int grow = bm + wm + mi * 16 + r0;
            int gcol = bn + wn + j * 8 + c0;
            float b0 = __ldg(bias + gcol), b1 = __ldg(bias + gcol + 1);
            float2 v0 = make_float2(acc[mi][j][0] + b0, acc[mi][j][1] + b1);
            float2 v1 = make_float2(acc[mi][j][2] + b0, acc[mi][j][3] + b1);
            *(float2*)(Out + (size_t)grow * DIM + gcol) = v0;
            *(float2*)(Out + (size_t)(grow + 8) * DIM + gcol) = v1;
        }
    }
}

// ---------------------------------------------------------------------------
// Flash-attention block: grid (S/64, H, B), 256 threads. (unchanged)
// ---------------------------------------------------------------------------
__global__ __launch_bounds__(256)
void attn_kernel(const float* __restrict__ Q, const float* __restrict__ K,
                 const float* __restrict__ V, float* __restrict__ H){
    extern __shared__ float sm[];
    float* Qs   = sm;
    float* Kt   = sm + 64 * 68;
    float* Vs   = sm + 2 * 64 * 68;
    float* Ss   = sm + 3 * 64 * 68;
    float* mrow = sm + 4 * 64 * 68;
    float* lrow = mrow + 64;
    float* frow = lrow + 64;

    int b = blockIdx.z, h = blockIdx.y, q0 = blockIdx.x * 64;
    int tid = threadIdx.x;
    int tx = tid & 15, ty = tid >> 4;
    int row_len = g_lens[b], col_len = g_lens[2 + b];

    const float* Qb = Q + ((size_t)b * SEQ + q0) * DIM + h * DK;
#pragma unroll
    for (int p = 0; p < 4; p++){
        int r = (tid >> 4) + p * 16;
        int c = (tid & 15) << 2;
        *(float4*)(Qs + r * 68 + c) = *(const float4*)(Qb + (size_t)r * DIM + c);
    }
    if (tid < 64){ mrow[tid] = -INFINITY; lrow[tid] = 0.f; }
    float o[4][4] = {};
    int kend = min(col_len, q0 + 64);
    __syncthreads();

    for (int kt = 0; kt < kend; kt += 64){
        const float* Kb = K + ((size_t)b * SEQ + kt) * DIM + h * DK;
        const float* Vb = V + ((size_t)b * SEQ + kt) * DIM + h * DK;
#pragma unroll
        for (int p = 0; p < 4; p++){
            int r = (tid >> 4) + p * 16;
            int c = (tid & 15) << 2;
            float4 kv = *(const float4*)(Kb + (size_t)r * DIM + c);
            Kt[(c + 0) * 68 + r] = kv.x; Kt[(c + 1) * 68 + r] = kv.y;
            Kt[(c + 2) * 68 + r] = kv.z; Kt[(c + 3) * 68 + r] = kv.w;
            *(float4*)(Vs + r * 68 + c) = *(const float4*)(Vb + (size_t)r * DIM + c);
        }
        __syncthreads();

        float s[4][4] = {};
#pragma unroll
        for (int d = 0; d < 64; d++){
            float a[4], bb[4];
#pragma unroll
            for (int i = 0; i < 4; i++) a[i] = Qs[(ty * 4 + i) * 68 + d];
#pragma unroll
            for (int j = 0; j < 4; j++) bb[j] = Kt[d * 68 + tx * 4 + j];
#pragma unroll
            for (int i = 0; i < 4; i++)
#pragma unroll
                for (int j = 0; j < 4; j++)
                    s[i][j] = fmaf(a[i], bb[j], s[i][j]);
        }
#pragma unroll
        for (int i = 0; i < 4; i++){
            int qg = q0 + ty * 4 + i;
#pragma unroll
            for (int j = 0; j < 4; j++){
                int kg = kt + tx * 4 + j;
                bool valid = (qg < row_len) && (kg < col_len) && (kg <= qg);
                Ss[(ty * 4 + i) * 68 + tx * 4 + j] =
                    valid ? s[i][j] * 0.125f : -INFINITY;
            }
        }
        __syncthreads();

        int warp = tid >> 5, lane = tid & 31;
        for (int r8 = 0; r8 < 8; r8++){
            int r = warp * 8 + r8;
            float v0 = Ss[r * 68 + lane], v1 = Ss[r * 68 + lane + 32];
            float mt = fmaxf(v0, v1);
#pragma unroll
            for (int off = 16; off > 0; off >>= 1)
                mt = fmaxf(mt, __shfl_xor_sync(0xffffffffu, mt, off));
            float mo = mrow[r];
            float mn = fmaxf(mo, mt);
            float p0, p1, fac;
            if (mn == -INFINITY){ p0 = 0.f; p1 = 0.f; fac = 1.f; }
            else {
                fac = (mo == -INFINITY) ? 0.f : __expf(mo - mn);
                p0  = (v0 == -INFINITY) ? 0.f : __expf(v0 - mn);
                p1  = (v1 == -INFINITY) ? 0.f : __expf(v1 - mn);
            }
            float sum = p0 + p1;
#pragma unroll
            for (int off = 16; off > 0; off >>= 1)
                sum += __shfl_xor_sync(0xffffffffu, sum, off);
            Ss[r * 68 + lane] = p0; Ss[r * 68 + lane + 32] = p1;
            if (lane == 0){ mrow[r] = mn; frow[r] = fac; lrow[r] = lrow[r] * fac + sum; }
        }
        __syncthreads();

        float f[4];
#pragma unroll
        for (int i = 0; i < 4; i++) f[i] = frow[ty * 4 + i];
#pragma unroll
        for (int i = 0; i < 4; i++)
#pragma unroll
            for (int j = 0; j < 4; j++) o[i][j] *= f[i];
#pragma unroll
        for (int k = 0; k < 64; k++){
            float a[4], bb[4];
#pragma unroll
            for (int i = 0; i < 4; i++) a[i] = Ss[(ty * 4 + i) * 68 + k];
#pragma unroll
            for (int j = 0; j < 4; j++) bb[j] = Vs[k * 68 + tx * 4 + j];
#pragma unroll
            for (int i = 0; i < 4; i++)
#pragma unroll
                for (int j = 0; j < 4; j++)
                    o[i][j] = fmaf(a[i], bb[j], o[i][j]);
        }
        __syncthreads();
    }

    float* Hb = H + ((size_t)b * SEQ + q0) * DIM + h * DK;
#pragma unroll
    for (int i = 0; i < 4; i++){
        float l = lrow[ty * 4 + i];
        float linv = (l > 0.f) ? 1.f / l : 0.f;
#pragma unroll
        for (int j = 0; j < 4; j++)
            Hb[(size_t)(ty * 4 + i) * DIM + tx * 4 + j] = o[i][j] * linv;
    }
}

// ---------------------------------------------------------------------------
extern "C" void kernel_launch(void* const* d_in, const int* in_sizes, int n_in,
                              void* d_out, int out_size){
    (void)in_sizes; (void)n_in; (void)out_size;
    const float* in_Q = (const float*)d_in[0];
    const float* in_K = (const float*)d_in[1];
    const float* in_V = (const float*)d_in[2];
    const int*   rowm = (const int*)  d_in[3];
    const int*   colm = (const int*)  d_in[4];
    const float* W_Q  = (const float*)d_in[5];
    const float* b_Q  = (const float*)d_in[6];
    const float* W_K  = (const float*)d_in[7];
    const float* b_K  = (const float*)d_in[8];
    const float* W_V  = (const float*)d_in[9];
    const float* b_V  = (const float*)d_in[10];
    const float* W_O  = (const float*)d_in[11];
    const float* b_O  = (const float*)d_in[12];
    float* out = (float*)d_out;

    float *gQ, *gK, *gV, *gH;
    cudaGetSymbolAddress((void**)&gQ, g_Q);
    cudaGetSymbolAddress((void**)&gK, g_K);
    cudaGetSymbolAddress((void**)&gV, g_V);
    cudaGetSymbolAddress((void**)&gH, g_H);

    lens_kernel<<<4, 256>>>(rowm, colm);

    cudaFuncSetAttribute(gemm_mma, cudaFuncAttributeMaxDynamicSharedMemorySize, GEMM_SMEM);
    dim3 gg(DIM / 64, MROWS / 128);
    gemm_mma<<<gg, 256, GEMM_SMEM>>>(in_Q, W_Q, b_Q, gQ);
    gemm_mma<<<gg, 256, GEMM_SMEM>>>(in_K, W_K, b_K, gK);
    gemm_mma<<<gg, 256, GEMM_SMEM>>>(in_V, W_V, b_V, gV);

    size_t smem_attn = (size_t)(4 * 64 * 68 + 192) * sizeof(float);
    cudaFuncSetAttribute(attn_kernel, cudaFuncAttributeMaxDynamicSharedMemorySize,
                         (int)smem_attn);
    attn_kernel<<<dim3(SEQ / 64, NH, BSZ), 256, smem_attn>>>(gQ, gK, gV, gH);

    gemm_mma<<<gg, 256, GEMM_SMEM>>>(gH, W_O, b_O, out);
}